// round 9
// baseline (speedup 1.0000x reference)
#include <cuda_runtime.h>
#include <cuda_fp16.h>
#include <math.h>
#include <stdint.h>

#define B_DIM 8192
#define IN_DIM 1024
#define H_DIM 1024
#define N_DIM 4096
#define K_DIM 2048
#define EPS 1e-6f

// GEMM tiling
#define TM 128
#define TN 256
#define KT 64                       // halves per k-tile (4 ksteps of k16)
#define KTILES (K_DIM / KT)         // 32
#define ROW_B 144                   // bytes per smem row: 128 data + 16 pad
#define A_STAGE_B (TM * ROW_B)      // 18432
#define B_STAGE_B (TN * ROW_B)      // 36864
#define STAGE_B (A_STAGE_B + B_STAGE_B)   // 55296
#define SMEM_TOTAL (2 * STAGE_B)          // 110592

// Scratch: fp16 operands (packed K=2048) + fp16 GEMM output (bias included)
__device__ __half g_A[(size_t)B_DIM * K_DIM];   // 33.5 MB
__device__ __half g_B[(size_t)N_DIM * K_DIM];   // 16.8 MB
__device__ __half g_v[(size_t)B_DIM * N_DIM];   // 67 MB

// ---------------------------------------------------------------------------
// Helpers
// ---------------------------------------------------------------------------
__device__ __forceinline__ uint32_t smem_u32(const void* p) {
    uint32_t a;
    asm("{ .reg .u64 t; cvta.to.shared.u64 t, %1; cvt.u32.u64 %0, t; }"
        : "=r"(a) : "l"(p));
    return a;
}
__device__ __forceinline__ void cp16(uint32_t smem, const void* g) {
    asm volatile("cp.async.cg.shared.global [%0], [%1], 16;"
                 :: "r"(smem), "l"(g));
}
#define LDSM_X4(r0, r1, r2, r3, addr)                                        \
    asm volatile("ldmatrix.sync.aligned.m8n8.x4.shared.b16 {%0,%1,%2,%3}, [%4];" \
                 : "=r"(r0), "=r"(r1), "=r"(r2), "=r"(r3) : "r"(addr))

#define MMA_F16(d, a, b)                                                     \
    asm volatile(                                                            \
        "mma.sync.aligned.m16n8k16.row.col.f32.f16.f16.f32 "                 \
        "{%0,%1,%2,%3}, {%4,%5,%6,%7}, {%8,%9}, {%0,%1,%2,%3};"              \
        : "+f"((d)[0]), "+f"((d)[1]), "+f"((d)[2]), "+f"((d)[3])             \
        : "r"((a)[0]), "r"((a)[1]), "r"((a)[2]), "r"((a)[3]),                \
          "r"((b)[0]), "r"((b)[1]))

// ---------------------------------------------------------------------------
// fp16 conversion pre-pass (merged): pack x|h -> g_A, w_ih|w_hh -> g_B.
// ---------------------------------------------------------------------------
__global__ __launch_bounds__(256)
void conv_AB(const float* __restrict__ x, const float* __restrict__ h,
             const float* __restrict__ w_ih, const float* __restrict__ w_hh)
{
    if (blockIdx.x < 16384) {
        size_t idx = (size_t)blockIdx.x * 256 + threadIdx.x;
        int r = (int)(idx >> 9);
        int k = ((int)idx & 511) * 4;
        const float* src = (k < IN_DIM) ? (x + (size_t)r * IN_DIM + k)
                                        : (h + (size_t)r * H_DIM + (k - IN_DIM));
        float4 v = *(const float4*)src;
        __half2 lo = __floats2half2_rn(v.x, v.y);
        __half2 hi = __floats2half2_rn(v.z, v.w);
        uint2 pk = make_uint2(*(uint32_t*)&lo, *(uint32_t*)&hi);
        *(uint2*)(g_A + (size_t)r * K_DIM + k) = pk;
    } else {
        size_t idx = (size_t)(blockIdx.x - 16384) * 256 + threadIdx.x;
        int r = (int)(idx >> 9);
        int k = ((int)idx & 511) * 4;
        const float* src = (k < IN_DIM) ? (w_ih + (size_t)r * IN_DIM + k)
                                        : (w_hh + (size_t)r * H_DIM + (k - IN_DIM));
        float4 v = *(const float4*)src;
        __half2 lo = __floats2half2_rn(v.x, v.y);
        __half2 hi = __floats2half2_rn(v.z, v.w);
        uint2 pk = make_uint2(*(uint32_t*)&lo, *(uint32_t*)&hi);
        *(uint2*)(g_B + (size_t)r * K_DIM + k) = pk;
    }
}

// ---------------------------------------------------------------------------
// fp16 mma.sync GEMM: v = A @ B^T + b_ih  (M=8192, N=4096, K=2048)
// CTA 128x256, KT=64 (4 ksteps), 2-stage double buffer, distance-1 prefetch.
// ---------------------------------------------------------------------------
__device__ __forceinline__ void load_stage(int kt, int s, int tid,
                                           uint32_t sbase, int bm, int bn)
{
    uint32_t sA = sbase + s * STAGE_B;
    uint32_t sB = sA + A_STAGE_B;
    int k0 = kt * KT;
    const __half* ga = g_A + (size_t)bm * K_DIM + k0;
    const __half* gb = g_B + (size_t)bn * K_DIM + k0;
#pragma unroll
    for (int i = 0; i < 4; i++) {               // A: 1024 16B units (128 x 8)
        int u = tid + i * 256;
        int row = u >> 3, q = u & 7;
        cp16(sA + (uint32_t)(row * ROW_B + q * 16),
             ga + (size_t)row * K_DIM + q * 8);
    }
#pragma unroll
    for (int i = 0; i < 8; i++) {               // B: 2048 16B units (256 x 8)
        int u = tid + i * 256;
        int row = u >> 3, q = u & 7;
        cp16(sB + (uint32_t)(row * ROW_B + q * 16),
             gb + (size_t)row * K_DIM + q * 8);
    }
    asm volatile("cp.async.commit_group;" ::: "memory");
}

__global__ __launch_bounds__(256, 1)
void lstm_gemm_f16(const float* __restrict__ b_ih)
{
    extern __shared__ __align__(128) char smem[];
    uint32_t sbase = smem_u32(smem);
    const int tid = threadIdx.x;
    const int wid = tid >> 5, lane = tid & 31;
    const int g = lane >> 2, c = lane & 3;
    const int warpM = (wid & 1) * 64;
    const int warpN = (wid >> 1) * 64;
    const int bn = blockIdx.x * TN;
    const int bm = blockIdx.y * TM;

    const int q  = lane >> 3;
    const int rr = lane & 7;
    const uint32_t laneA = (uint32_t)(((q & 1) * 8 + rr) * ROW_B + (q >> 1) * 16);
    const uint32_t laneB = (uint32_t)(((q >> 1) * 8 + rr) * ROW_B + (q & 1) * 16);

    float acc[4][8][4];
#pragma unroll
    for (int mt = 0; mt < 4; mt++)
#pragma unroll
        for (int nt = 0; nt < 8; nt++)
#pragma unroll
            for (int r = 0; r < 4; r++)
                acc[mt][nt][r] = 0.0f;

    load_stage(0, 0, tid, sbase, bm, bn);

    for (int kt = 0; kt < KTILES; kt++) {
        int s = kt & 1;
        asm volatile("cp.async.wait_group 0;" ::: "memory");
        // barrier: publishes stage s AND confirms all warps done with stage s^1
        __syncthreads();

        if (kt + 1 < KTILES)
            load_stage(kt + 1, s ^ 1, tid, sbase, bm, bn);

        uint32_t stA = sbase + s * STAGE_B;
        uint32_t stB = stA + A_STAGE_B;

#pragma unroll
        for (int ks = 0; ks < 4; ks++) {
            uint32_t a[4][4], b[4][4];
#pragma unroll
            for (int mt = 0; mt < 4; mt++) {
                uint32_t addr = stA + (uint32_t)((warpM + mt * 16) * ROW_B
                                                 + ks * 32) + laneA;
                LDSM_X4(a[mt][0], a[mt][1], a[mt][2], a[mt][3], addr);
            }
#pragma unroll
            for (int np = 0; np < 4; np++) {
                uint32_t addr = stB + (uint32_t)((warpN + np * 16) * ROW_B
                                                 + ks * 32) + laneB;
                LDSM_X4(b[np][0], b[np][1], b[np][2], b[np][3], addr);
            }
#pragma unroll
            for (int mt = 0; mt < 4; mt++)
#pragma unroll
                for (int nt = 0; nt < 8; nt++) {
                    uint32_t bf[2] = { b[nt >> 1][(nt & 1) * 2],
                                       b[nt >> 1][(nt & 1) * 2 + 1] };
                    MMA_F16(acc[mt][nt], a[mt], bf);
                }
        }
    }

    // Store C as fp16 with bias folded in (fp32 add before convert).
#pragma unroll
    for (int nt = 0; nt < 8; nt++) {
        int cn = bn + warpN + nt * 8 + 2 * c;
        float2 bi = *(const float2*)&b_ih[cn];
#pragma unroll
        for (int mt = 0; mt < 4; mt++) {
            int r0 = bm + warpM + mt * 16 + g;
            __half2 h01 = __floats2half2_rn(acc[mt][nt][0] + bi.x,
                                            acc[mt][nt][1] + bi.y);
            __half2 h23 = __floats2half2_rn(acc[mt][nt][2] + bi.x,
                                            acc[mt][nt][3] + bi.y);
            *(__half2*)(g_v + (size_t)r0 * N_DIM + cn)       = h01;
            *(__half2*)(g_v + (size_t)(r0 + 8) * N_DIM + cn) = h23;
        }
    }
}

// ---------------------------------------------------------------------------
// Epilogue: 2 rows per CTA, fp16 v loads (bias pre-added), combined
// reductions, float4 I/O, MUFU activations.
// ---------------------------------------------------------------------------
__device__ __forceinline__ float sigmoidf_(float v) {
    return 1.0f / (1.0f + __expf(-v));
}
__device__ __forceinline__ float tanhf_(float v) {
    return 2.0f / (1.0f + __expf(-2.0f * v)) - 1.0f;
}

__global__ __launch_bounds__(256, 4)
void lstm_epilogue_kernel(const float* __restrict__ c,
                          const float* __restrict__ gamma_ifgo,
                          const float* __restrict__ beta_ifgo,
                          const float* __restrict__ gamma_c,
                          const float* __restrict__ beta_c,
                          float* __restrict__ out_h,
                          float* __restrict__ out_c)
{
    __shared__ float shred[128];
    __shared__ float tot[20];

    const int b0   = blockIdx.x * 2;
    const int tid  = threadIdx.x;
    const int lane = tid & 31, warp = tid >> 5;

    const uint2* v0 = (const uint2*)&g_v[(size_t)b0 * N_DIM];
    const uint2* v1 = (const uint2*)&g_v[(size_t)(b0 + 1) * N_DIM];

    // ---- load both rows' gates; per-row per-gate (sum, sumsq) ----
    float gate[2][4][4];
    float red[16];
#pragma unroll
    for (int gi = 0; gi < 4; gi++) {
        uint2 p0 = v0[gi * 256 + tid];
        uint2 p1 = v1[gi * 256 + tid];
        float2 a0l = __half22float2(*(__half2*)&p0.x);
        float2 a0h = __half22float2(*(__half2*)&p0.y);
        float2 a1l = __half22float2(*(__half2*)&p1.x);
        float2 a1h = __half22float2(*(__half2*)&p1.y);
        gate[0][gi][0] = a0l.x; gate[0][gi][1] = a0l.y;
        gate[0][gi][2] = a0h.x; gate[0][gi][3] = a0h.y;
        gate[1][gi][0] = a1l.x; gate[1][gi][1] = a1l.y;
        gate[1][gi][2] = a1h.x; gate[1][gi][3] = a1h.y;
#pragma unroll
        for (int row = 0; row < 2; row++) {
            float s  = gate[row][gi][0] + gate[row][gi][1]
                     + gate[row][gi][2] + gate[row][gi][3];
            float sq = gate[row][gi][0] * gate[row][gi][0]
                     + gate[row][gi][1] * gate[row][gi][1]
                     + gate[row][gi][2] * gate[row][gi][2]
                     + gate[row][gi][3] * gate[row][gi][3];
            red[row * 8 + gi * 2]     = s;
            red[row * 8 + gi * 2 + 1] = sq;
        }
    }

    // ---- combined reduction of 16 values ----
#pragma unroll
    for (int v = 0; v < 16; v++)
#pragma unroll
        for (int off = 16; off > 0; off >>= 1)
            red[v] += __shfl_down_sync(0xFFFFFFFFu, red[v], off);
    if (lane == 0) {
#pragma unroll
        for (int v = 0; v < 16; v++) shred[warp * 16 + v] = red[v];
    }
    __syncthreads();
    if (tid < 32) {
        int v = lane & 15, half = lane >> 4;
        float t = shred[(half * 4 + 0) * 16 + v] + shred[(half * 4 + 1) * 16 + v]
                + shred[(half * 4 + 2) * 16 + v] + shred[(half * 4 + 3) * 16 + v];
        t += __shfl_down_sync(0xFFFFFFFFu, t, 16);
        if (lane < 16) tot[lane] = t;
    }
    __syncthreads();

    // ---- apply gate LayerNorms ----
    const float4* gam4 = (const float4*)gamma_ifgo;
    const float4* bet4 = (const float4*)beta_ifgo;
#pragma unroll
    for (int gi = 0; gi < 4; gi++) {
        float4 ga = gam4[gi * 256 + tid];
        float4 be = bet4[gi * 256 + tid];
        float gav[4] = { ga.x, ga.y, ga.z, ga.w };
        float bev[4] = { be.x, be.y, be.z, be.w };
#pragma unroll
        for (int row = 0; row < 2; row++) {
            float s  = tot[row * 8 + gi * 2];
            float sq = tot[row * 8 + gi * 2 + 1];
            float mean = s * (1.0f / H_DIM);
            float var  = (sq - (float)H_DIM * mean * mean) * (1.0f / (H_DIM - 1));
            var = fmaxf(var, 0.0f);
            float inv = 1.0f / (sqrtf(var) + EPS);
#pragma unroll
            for (int r = 0; r < 4; r++)
                gate[row][gi][r] = gav[r] * (gate[row][gi][r] - mean) * inv + bev[r];
        }
    }

    // ---- LSTM pointwise ----
    float nc[2][4], og[2][4];
    float red2[4];
    float4 c0 = ((const float4*)(c + (size_t)b0 * H_DIM))[tid];
    float4 c1 = ((const float4*)(c + (size_t)(b0 + 1) * H_DIM))[tid];
    float cv[2][4] = { { c0.x, c0.y, c0.z, c0.w }, { c1.x, c1.y, c1.z, c1.w } };
#pragma unroll
    for (int row = 0; row < 2; row++) {
        float s = 0.0f, sq = 0.0f;
#pragma unroll
        for (int r = 0; r < 4; r++) {
            float iv = gate[row][0][r];
            float fv = gate[row][1][r] + 1.0f;
            float gv = gate[row][2][r];
            og[row][r] = gate[row][3][r];
            float v = cv[row][r] * sigmoidf_(fv) + sigmoidf_(iv) * tanhf_(gv);
            nc[row][r] = v;
            s += v; sq += v * v;
        }
        red2[row * 2] = s; red2[row * 2 + 1] = sq;
    }

    // ---- combined cell-LN reduction ----
#pragma unroll
    for (int v = 0; v < 4; v++)
#pragma unroll
        for (int off = 16; off > 0; off >>= 1)
            red2[v] += __shfl_down_sync(0xFFFFFFFFu, red2[v], off);
    if (lane == 0) {
#pragma unroll
        for (int v = 0; v < 4; v++) shred[warp * 4 + v] = red2[v];
    }
    __syncthreads();
    if (tid < 32) {
        int v = lane & 3, p = lane >> 2;
        float t = shred[p * 4 + v];
        t += __shfl_down_sync(0xFFFFFFFFu, t, 16);
        t += __shfl_down_sync(0xFFFFFFFFu, t, 8);
        t += __shfl_down_sync(0xFFFFFFFFu, t, 4);
        if (lane < 4) tot[16 + lane] = t;
    }
    __syncthreads();

    // ---- cell LN apply + outputs ----
    float4 gc = ((const float4*)gamma_c)[tid];
    float4 bc = ((const float4*)beta_c)[tid];
    float gcv[4] = { gc.x, gc.y, gc.z, gc.w };
    float bcv[4] = { bc.x, bc.y, bc.z, bc.w };
#pragma unroll
    for (int row = 0; row < 2; row++) {
        float mean = tot[16 + row * 2] * (1.0f / H_DIM);
        float var  = (tot[16 + row * 2 + 1] - (float)H_DIM * mean * mean)
                   * (1.0f / (H_DIM - 1));
        var = fmaxf(var, 0.0f);
        float inv = 1.0f / (sqrtf(var) + EPS);
        float4 oc, oh;
        float* ocp = &oc.x;
        float* ohp = &oh.x;
#pragma unroll
        for (int r = 0; r < 4; r++) {
            float ncv = gcv[r] * (nc[row][r] - mean) * inv + bcv[r];
            ocp[r] = ncv;
            ohp[r] = tanhf_(ncv) * sigmoidf_(og[row][r]);
        }
        ((float4*)(out_c + (size_t)(b0 + row) * H_DIM))[tid] = oc;
        ((float4*)(out_h + (size_t)(b0 + row) * H_DIM))[tid] = oh;
    }
}

// ---------------------------------------------------------------------------
// Launch
// ---------------------------------------------------------------------------
extern "C" void kernel_launch(void* const* d_in, const int* in_sizes, int n_in,
                              void* d_out, int out_size)
{
    const float* x          = (const float*)d_in[0];
    const float* h          = (const float*)d_in[1];
    const float* c          = (const float*)d_in[2];
    const float* w_ih       = (const float*)d_in[3];
    const float* b_ih       = (const float*)d_in[4];
    const float* w_hh       = (const float*)d_in[5];
    const float* gamma_ifgo = (const float*)d_in[6];
    const float* beta_ifgo  = (const float*)d_in[7];
    const float* gamma_c    = (const float*)d_in[8];
    const float* beta_c     = (const float*)d_in[9];

    float* out_h = (float*)d_out;
    float* out_c = (float*)d_out + (size_t)B_DIM * H_DIM;

    cudaFuncSetAttribute(lstm_gemm_f16,
                         cudaFuncAttributeMaxDynamicSharedMemorySize, SMEM_TOTAL);

    conv_AB<<<24576, 256>>>(x, h, w_ih, w_hh);

    dim3 grid(N_DIM / TN, B_DIM / TM);  // (16, 64)
    lstm_gemm_f16<<<grid, 256, SMEM_TOTAL>>>(b_ih);

    lstm_epilogue_kernel<<<B_DIM / 2, 256>>>(c, gamma_ifgo, beta_ifgo,
                                             gamma_c, beta_c, out_h, out_c);
}

// round 10
// speedup vs baseline: 1.0031x; 1.0031x over previous
#include <cuda_runtime.h>
#include <cuda_fp16.h>
#include <math.h>
#include <stdint.h>

#define B_DIM 8192
#define IN_DIM 1024
#define H_DIM 1024
#define N_DIM 4096
#define K_DIM 2048
#define EPS 1e-6f

// GEMM tiling
#define TM 128
#define TN 256
#define KT 64                       // halves per k-tile (4 ksteps of k16)
#define KTILES (K_DIM / KT)         // 32
#define ROW_B 144                   // bytes per smem row: 128 data + 16 pad
#define A_STAGE_B (TM * ROW_B)      // 18432
#define B_STAGE_B (TN * ROW_B)      // 36864
#define STAGE_B (A_STAGE_B + B_STAGE_B)   // 55296
#define SMEM_TOTAL (2 * STAGE_B)          // 110592

// Scratch: fp16 operands (packed K=2048) + fp16 GEMM output (bias included)
__device__ __half g_A[(size_t)B_DIM * K_DIM];   // 33.5 MB
__device__ __half g_B[(size_t)N_DIM * K_DIM];   // 16.8 MB
__device__ __half g_v[(size_t)B_DIM * N_DIM];   // 67 MB

// ---------------------------------------------------------------------------
// Helpers
// ---------------------------------------------------------------------------
__device__ __forceinline__ uint32_t smem_u32(const void* p) {
    uint32_t a;
    asm("{ .reg .u64 t; cvta.to.shared.u64 t, %1; cvt.u32.u64 %0, t; }"
        : "=r"(a) : "l"(p));
    return a;
}
__device__ __forceinline__ void cp16(uint32_t smem, const void* g) {
    asm volatile("cp.async.cg.shared.global [%0], [%1], 16;"
                 :: "r"(smem), "l"(g));
}
#define LDSM_X4(r0, r1, r2, r3, addr)                                        \
    asm volatile("ldmatrix.sync.aligned.m8n8.x4.shared.b16 {%0,%1,%2,%3}, [%4];" \
                 : "=r"(r0), "=r"(r1), "=r"(r2), "=r"(r3) : "r"(addr))

#define MMA_F16(d, a, b)                                                     \
    asm volatile(                                                            \
        "mma.sync.aligned.m16n8k16.row.col.f32.f16.f16.f32 "                 \
        "{%0,%1,%2,%3}, {%4,%5,%6,%7}, {%8,%9}, {%0,%1,%2,%3};"              \
        : "+f"((d)[0]), "+f"((d)[1]), "+f"((d)[2]), "+f"((d)[3])             \
        : "r"((a)[0]), "r"((a)[1]), "r"((a)[2]), "r"((a)[3]),                \
          "r"((b)[0]), "r"((b)[1]))

// ---------------------------------------------------------------------------
// fp16 conversion pre-pass (merged): pack x|h -> g_A, w_ih|w_hh -> g_B.
// ---------------------------------------------------------------------------
__global__ __launch_bounds__(256)
void conv_AB(const float* __restrict__ x, const float* __restrict__ h,
             const float* __restrict__ w_ih, const float* __restrict__ w_hh)
{
    if (blockIdx.x < 16384) {
        size_t idx = (size_t)blockIdx.x * 256 + threadIdx.x;
        int r = (int)(idx >> 9);
        int k = ((int)idx & 511) * 4;
        const float* src = (k < IN_DIM) ? (x + (size_t)r * IN_DIM + k)
                                        : (h + (size_t)r * H_DIM + (k - IN_DIM));
        float4 v = *(const float4*)src;
        __half2 lo = __floats2half2_rn(v.x, v.y);
        __half2 hi = __floats2half2_rn(v.z, v.w);
        uint2 pk = make_uint2(*(uint32_t*)&lo, *(uint32_t*)&hi);
        *(uint2*)(g_A + (size_t)r * K_DIM + k) = pk;
    } else {
        size_t idx = (size_t)(blockIdx.x - 16384) * 256 + threadIdx.x;
        int r = (int)(idx >> 9);
        int k = ((int)idx & 511) * 4;
        const float* src = (k < IN_DIM) ? (w_ih + (size_t)r * IN_DIM + k)
                                        : (w_hh + (size_t)r * H_DIM + (k - IN_DIM));
        float4 v = *(const float4*)src;
        __half2 lo = __floats2half2_rn(v.x, v.y);
        __half2 hi = __floats2half2_rn(v.z, v.w);
        uint2 pk = make_uint2(*(uint32_t*)&lo, *(uint32_t*)&hi);
        *(uint2*)(g_B + (size_t)r * K_DIM + k) = pk;
    }
}

// ---------------------------------------------------------------------------
// fp16 mma.sync GEMM: v = A @ B^T + b_ih  (M=8192, N=4096, K=2048)
// CTA 128x256, KT=64 (4 ksteps), 2-stage double buffer, distance-1 prefetch.
// ---------------------------------------------------------------------------
__device__ __forceinline__ void load_stage(int kt, int s, int tid,
                                           uint32_t sbase, int bm, int bn)
{
    uint32_t sA = sbase + s * STAGE_B;
    uint32_t sB = sA + A_STAGE_B;
    int k0 = kt * KT;
    const __half* ga = g_A + (size_t)bm * K_DIM + k0;
    const __half* gb = g_B + (size_t)bn * K_DIM + k0;
#pragma unroll
    for (int i = 0; i < 4; i++) {               // A: 1024 16B units (128 x 8)
        int u = tid + i * 256;
        int row = u >> 3, q = u & 7;
        cp16(sA + (uint32_t)(row * ROW_B + q * 16),
             ga + (size_t)row * K_DIM + q * 8);
    }
#pragma unroll
    for (int i = 0; i < 8; i++) {               // B: 2048 16B units (256 x 8)
        int u = tid + i * 256;
        int row = u >> 3, q = u & 7;
        cp16(sB + (uint32_t)(row * ROW_B + q * 16),
             gb + (size_t)row * K_DIM + q * 8);
    }
    asm volatile("cp.async.commit_group;" ::: "memory");
}

__global__ __launch_bounds__(256, 1)
void lstm_gemm_f16(const float* __restrict__ b_ih)
{
    extern __shared__ __align__(128) char smem[];
    uint32_t sbase = smem_u32(smem);
    const int tid = threadIdx.x;
    const int wid = tid >> 5, lane = tid & 31;
    const int g = lane >> 2, c = lane & 3;
    const int warpM = (wid & 1) * 64;
    const int warpN = (wid >> 1) * 64;
    const int bn = blockIdx.x * TN;
    const int bm = blockIdx.y * TM;

    const int q  = lane >> 3;
    const int rr = lane & 7;
    const uint32_t laneA = (uint32_t)(((q & 1) * 8 + rr) * ROW_B + (q >> 1) * 16);
    const uint32_t laneB = (uint32_t)(((q >> 1) * 8 + rr) * ROW_B + (q & 1) * 16);

    float acc[4][8][4];
#pragma unroll
    for (int mt = 0; mt < 4; mt++)
#pragma unroll
        for (int nt = 0; nt < 8; nt++)
#pragma unroll
            for (int r = 0; r < 4; r++)
                acc[mt][nt][r] = 0.0f;

    load_stage(0, 0, tid, sbase, bm, bn);

    for (int kt = 0; kt < KTILES; kt++) {
        int s = kt & 1;
        asm volatile("cp.async.wait_group 0;" ::: "memory");
        // barrier: publishes stage s AND confirms all warps done with stage s^1
        __syncthreads();

        if (kt + 1 < KTILES)
            load_stage(kt + 1, s ^ 1, tid, sbase, bm, bn);

        uint32_t stA = sbase + s * STAGE_B;
        uint32_t stB = stA + A_STAGE_B;

#pragma unroll
        for (int ks = 0; ks < 4; ks++) {
            uint32_t a[4][4], b[4][4];
#pragma unroll
            for (int mt = 0; mt < 4; mt++) {
                uint32_t addr = stA + (uint32_t)((warpM + mt * 16) * ROW_B
                                                 + ks * 32) + laneA;
                LDSM_X4(a[mt][0], a[mt][1], a[mt][2], a[mt][3], addr);
            }
#pragma unroll
            for (int np = 0; np < 4; np++) {
                uint32_t addr = stB + (uint32_t)((warpN + np * 16) * ROW_B
                                                 + ks * 32) + laneB;
                LDSM_X4(b[np][0], b[np][1], b[np][2], b[np][3], addr);
            }
#pragma unroll
            for (int mt = 0; mt < 4; mt++)
#pragma unroll
                for (int nt = 0; nt < 8; nt++) {
                    uint32_t bf[2] = { b[nt >> 1][(nt & 1) * 2],
                                       b[nt >> 1][(nt & 1) * 2 + 1] };
                    MMA_F16(acc[mt][nt], a[mt], bf);
                }
        }
    }

    // Store C as fp16 with bias folded in (fp32 add before convert).
#pragma unroll
    for (int nt = 0; nt < 8; nt++) {
        int cn = bn + warpN + nt * 8 + 2 * c;
        float2 bi = *(const float2*)&b_ih[cn];
#pragma unroll
        for (int mt = 0; mt < 4; mt++) {
            int r0 = bm + warpM + mt * 16 + g;
            __half2 h01 = __floats2half2_rn(acc[mt][nt][0] + bi.x,
                                            acc[mt][nt][1] + bi.y);
            __half2 h23 = __floats2half2_rn(acc[mt][nt][2] + bi.x,
                                            acc[mt][nt][3] + bi.y);
            *(__half2*)(g_v + (size_t)r0 * N_DIM + cn)       = h01;
            *(__half2*)(g_v + (size_t)(r0 + 8) * N_DIM + cn) = h23;
        }
    }
}

// ---------------------------------------------------------------------------
// Epilogue: 2 rows per CTA, fp16 v loads (bias pre-added), combined
// reductions, float4 I/O, MUFU activations.
// ---------------------------------------------------------------------------
__device__ __forceinline__ float sigmoidf_(float v) {
    return 1.0f / (1.0f + __expf(-v));
}
__device__ __forceinline__ float tanhf_(float v) {
    return 2.0f / (1.0f + __expf(-2.0f * v)) - 1.0f;
}

__global__ __launch_bounds__(256, 4)
void lstm_epilogue_kernel(const float* __restrict__ c,
                          const float* __restrict__ gamma_ifgo,
                          const float* __restrict__ beta_ifgo,
                          const float* __restrict__ gamma_c,
                          const float* __restrict__ beta_c,
                          float* __restrict__ out_h,
                          float* __restrict__ out_c)
{
    __shared__ float shred[128];
    __shared__ float tot[20];

    const int b0   = blockIdx.x * 2;
    const int tid  = threadIdx.x;
    const int lane = tid & 31, warp = tid >> 5;

    const uint2* v0 = (const uint2*)&g_v[(size_t)b0 * N_DIM];
    const uint2* v1 = (const uint2*)&g_v[(size_t)(b0 + 1) * N_DIM];

    // ---- load both rows' gates; per-row per-gate (sum, sumsq) ----
    float gate[2][4][4];
    float red[16];
#pragma unroll
    for (int gi = 0; gi < 4; gi++) {
        uint2 p0 = v0[gi * 256 + tid];
        uint2 p1 = v1[gi * 256 + tid];
        float2 a0l = __half22float2(*(__half2*)&p0.x);
        float2 a0h = __half22float2(*(__half2*)&p0.y);
        float2 a1l = __half22float2(*(__half2*)&p1.x);
        float2 a1h = __half22float2(*(__half2*)&p1.y);
        gate[0][gi][0] = a0l.x; gate[0][gi][1] = a0l.y;
        gate[0][gi][2] = a0h.x; gate[0][gi][3] = a0h.y;
        gate[1][gi][0] = a1l.x; gate[1][gi][1] = a1l.y;
        gate[1][gi][2] = a1h.x; gate[1][gi][3] = a1h.y;
#pragma unroll
        for (int row = 0; row < 2; row++) {
            float s  = gate[row][gi][0] + gate[row][gi][1]
                     + gate[row][gi][2] + gate[row][gi][3];
            float sq = gate[row][gi][0] * gate[row][gi][0]
                     + gate[row][gi][1] * gate[row][gi][1]
                     + gate[row][gi][2] * gate[row][gi][2]
                     + gate[row][gi][3] * gate[row][gi][3];
            red[row * 8 + gi * 2]     = s;
            red[row * 8 + gi * 2 + 1] = sq;
        }
    }

    // ---- combined reduction of 16 values ----
#pragma unroll
    for (int v = 0; v < 16; v++)
#pragma unroll
        for (int off = 16; off > 0; off >>= 1)
            red[v] += __shfl_down_sync(0xFFFFFFFFu, red[v], off);
    if (lane == 0) {
#pragma unroll
        for (int v = 0; v < 16; v++) shred[warp * 16 + v] = red[v];
    }
    __syncthreads();
    if (tid < 32) {
        int v = lane & 15, half = lane >> 4;
        float t = shred[(half * 4 + 0) * 16 + v] + shred[(half * 4 + 1) * 16 + v]
                + shred[(half * 4 + 2) * 16 + v] + shred[(half * 4 + 3) * 16 + v];
        t += __shfl_down_sync(0xFFFFFFFFu, t, 16);
        if (lane < 16) tot[lane] = t;
    }
    __syncthreads();

    // ---- apply gate LayerNorms ----
    const float4* gam4 = (const float4*)gamma_ifgo;
    const float4* bet4 = (const float4*)beta_ifgo;
#pragma unroll
    for (int gi = 0; gi < 4; gi++) {
        float4 ga = gam4[gi * 256 + tid];
        float4 be = bet4[gi * 256 + tid];
        float gav[4] = { ga.x, ga.y, ga.z, ga.w };
        float bev[4] = { be.x, be.y, be.z, be.w };
#pragma unroll
        for (int row = 0; row < 2; row++) {
            float s  = tot[row * 8 + gi * 2];
            float sq = tot[row * 8 + gi * 2 + 1];
            float mean = s * (1.0f / H_DIM);
            float var  = (sq - (float)H_DIM * mean * mean) * (1.0f / (H_DIM - 1));
            var = fmaxf(var, 0.0f);
            float inv = 1.0f / (sqrtf(var) + EPS);
#pragma unroll
            for (int r = 0; r < 4; r++)
                gate[row][gi][r] = gav[r] * (gate[row][gi][r] - mean) * inv + bev[r];
        }
    }

    // ---- LSTM pointwise ----
    float nc[2][4], og[2][4];
    float red2[4];
    float4 c0 = ((const float4*)(c + (size_t)b0 * H_DIM))[tid];
    float4 c1 = ((const float4*)(c + (size_t)(b0 + 1) * H_DIM))[tid];
    float cv[2][4] = { { c0.x, c0.y, c0.z, c0.w }, { c1.x, c1.y, c1.z, c1.w } };
#pragma unroll
    for (int row = 0; row < 2; row++) {
        float s = 0.0f, sq = 0.0f;
#pragma unroll
        for (int r = 0; r < 4; r++) {
            float iv = gate[row][0][r];
            float fv = gate[row][1][r] + 1.0f;
            float gv = gate[row][2][r];
            og[row][r] = gate[row][3][r];
            float v = cv[row][r] * sigmoidf_(fv) + sigmoidf_(iv) * tanhf_(gv);
            nc[row][r] = v;
            s += v; sq += v * v;
        }
        red2[row * 2] = s; red2[row * 2 + 1] = sq;
    }

    // ---- combined cell-LN reduction ----
#pragma unroll
    for (int v = 0; v < 4; v++)
#pragma unroll
        for (int off = 16; off > 0; off >>= 1)
            red2[v] += __shfl_down_sync(0xFFFFFFFFu, red2[v], off);
    if (lane == 0) {
#pragma unroll
        for (int v = 0; v < 4; v++) shred[warp * 4 + v] = red2[v];
    }
    __syncthreads();
    if (tid < 32) {
        int v = lane & 3, p = lane >> 2;
        float t = shred[p * 4 + v];
        t += __shfl_down_sync(0xFFFFFFFFu, t, 16);
        t += __shfl_down_sync(0xFFFFFFFFu, t, 8);
        t += __shfl_down_sync(0xFFFFFFFFu, t, 4);
        if (lane < 4) tot[16 + lane] = t;
    }
    __syncthreads();

    // ---- cell LN apply + outputs ----
    float4 gc = ((const float4*)gamma_c)[tid];
    float4 bc = ((const float4*)beta_c)[tid];
    float gcv[4] = { gc.x, gc.y, gc.z, gc.w };
    float bcv[4] = { bc.x, bc.y, bc.z, bc.w };
#pragma unroll
    for (int row = 0; row < 2; row++) {
        float mean = tot[16 + row * 2] * (1.0f / H_DIM);
        float var  = (tot[16 + row * 2 + 1] - (float)H_DIM * mean * mean)
                   * (1.0f / (H_DIM - 1));
        var = fmaxf(var, 0.0f);
        float inv = 1.0f / (sqrtf(var) + EPS);
        float4 oc, oh;
        float* ocp = &oc.x;
        float* ohp = &oh.x;
#pragma unroll
        for (int r = 0; r < 4; r++) {
            float ncv = gcv[r] * (nc[row][r] - mean) * inv + bcv[r];
            ocp[r] = ncv;
            ohp[r] = tanhf_(ncv) * sigmoidf_(og[row][r]);
        }
        ((float4*)(out_c + (size_t)(b0 + row) * H_DIM))[tid] = oc;
        ((float4*)(out_h + (size_t)(b0 + row) * H_DIM))[tid] = oh;
    }
}

// ---------------------------------------------------------------------------
// Launch
// ---------------------------------------------------------------------------
extern "C" void kernel_launch(void* const* d_in, const int* in_sizes, int n_in,
                              void* d_out, int out_size)
{
    const float* x          = (const float*)d_in[0];
    const float* h          = (const float*)d_in[1];
    const float* c          = (const float*)d_in[2];
    const float* w_ih       = (const float*)d_in[3];
    const float* b_ih       = (const float*)d_in[4];
    const float* w_hh       = (const float*)d_in[5];
    const float* gamma_ifgo = (const float*)d_in[6];
    const float* beta_ifgo  = (const float*)d_in[7];
    const float* gamma_c    = (const float*)d_in[8];
    const float* beta_c     = (const float*)d_in[9];

    float* out_h = (float*)d_out;
    float* out_c = (float*)d_out + (size_t)B_DIM * H_DIM;

    cudaFuncSetAttribute(lstm_gemm_f16,
                         cudaFuncAttributeMaxDynamicSharedMemorySize, SMEM_TOTAL);

    conv_AB<<<24576, 256>>>(x, h, w_ih, w_hh);

    dim3 grid(N_DIM / TN, B_DIM / TM);  // (16, 64)
    lstm_gemm_f16<<<grid, 256, SMEM_TOTAL>>>(b_ih);

    lstm_epilogue_kernel<<<B_DIM / 2, 256>>>(c, gamma_ifgo, beta_ifgo,
                                             gamma_c, beta_c, out_h, out_c);
}